// round 1
// baseline (speedup 1.0000x reference)
#include <cuda_runtime.h>
#include <math.h>

#define L 2048
#define H 512
#define NSTATE 32
#define NL 4
#define INDIM 4
#define OUTDIM 3

// Scratch (allocation-free rule: device globals)
__device__ float g_h[L * H];   // residual stream
__device__ float g_u[L * H];   // layernorm output
__device__ float g_y[L * H];   // gelu(scan output)

// ---------------------------------------------------------------------------
// Encoder: h[t][j] = enc_b[j] + sum_k x[t][k] * enc_w[j][k]   (IN = 4)
// ---------------------------------------------------------------------------
__global__ void enc_kernel(const float* __restrict__ x,
                           const float* __restrict__ w,
                           const float* __restrict__ b) {
    int t = blockIdx.x;
    int j = threadIdx.x;
    float4 xr = *(const float4*)(x + t * INDIM);
    float4 wr = *(const float4*)(w + j * INDIM);
    g_h[t * H + j] = b[j] + xr.x * wr.x + xr.y * wr.y + xr.z * wr.z + xr.w * wr.w;
}

// ---------------------------------------------------------------------------
// LayerNorm over H=512 per row. 256 threads, 2 elems each.
// ---------------------------------------------------------------------------
__global__ void ln_kernel(const float* __restrict__ nw,
                          const float* __restrict__ nb) {
    int t = blockIdx.x;
    int tid = threadIdx.x;
    float v0 = g_h[t * H + tid];
    float v1 = g_h[t * H + tid + 256];
    float s = v0 + v1;
    float sq = v0 * v0 + v1 * v1;
#pragma unroll
    for (int off = 16; off; off >>= 1) {
        s  += __shfl_xor_sync(0xffffffffu, s, off);
        sq += __shfl_xor_sync(0xffffffffu, sq, off);
    }
    __shared__ float ss[8], ssq[8];
    int w = tid >> 5;
    if ((tid & 31) == 0) { ss[w] = s; ssq[w] = sq; }
    __syncthreads();
    __shared__ float m_sh, r_sh;
    if (tid == 0) {
        float S = 0.f, Q = 0.f;
#pragma unroll
        for (int i = 0; i < 8; i++) { S += ss[i]; Q += ssq[i]; }
        float m = S * (1.0f / H);
        float var = Q * (1.0f / H) - m * m;
        m_sh = m;
        r_sh = rsqrtf(var + 1e-5f);
    }
    __syncthreads();
    float m = m_sh, r = r_sh;
    g_u[t * H + tid]       = (v0 - m) * r * nw[tid]       + nb[tid];
    g_u[t * H + tid + 256] = (v1 - m) * r * nw[tid + 256] + nb[tid + 256];
}

// ---------------------------------------------------------------------------
// S4 scan: one warp per channel, one lane per state (N=32).
// Batched 8-step butterfly reduction to pipeline SHFL latency.
// Writes gelu(y) to g_y.
// ---------------------------------------------------------------------------
__device__ __forceinline__ float gelu_tanh(float yv) {
    float z = 0.7978845608028654f * fmaf(0.044715f * yv, yv * yv, yv);
    z = fminf(fmaxf(z, -15.f), 15.f);
    float e = __expf(2.f * z);
    float th = (e - 1.f) / (e + 1.f);
    return 0.5f * yv * (1.f + th);
}

__global__ void scan_kernel(const float* __restrict__ lre_, const float* __restrict__ lim_,
                            const float* __restrict__ bre_, const float* __restrict__ bim_,
                            const float* __restrict__ cre_, const float* __restrict__ cim_,
                            const float* __restrict__ dvec, const float* __restrict__ lstep_) {
    int warp = (blockIdx.x * blockDim.x + threadIdx.x) >> 5;
    int lane = threadIdx.x & 31;
    int ch = warp;                 // 512 warps total
    int idx = ch * NSTATE + lane;

    float lre = lre_[idx], lim = lim_[idx];
    float step = __expf(lstep_[ch]);
    float s2 = 0.5f * step;
    // BL = 1 / (1 - s2*Lam)
    float dr = 1.f - s2 * lre, di = -s2 * lim;
    float inv = 1.f / (dr * dr + di * di);
    float blr = dr * inv, bli = -di * inv;
    // Abar = BL * (1 + s2*Lam)
    float nr = 1.f + s2 * lre, ni = s2 * lim;
    float are = blr * nr - bli * ni;
    float aim = blr * ni + bli * nr;
    // Bbar = BL * step * B
    float br = bre_[idx], bi = bim_[idx];
    float bbr = step * (blr * br - bli * bi);
    float bbi = step * (blr * bi + bli * br);
    float cre = cre_[idx], cim = cim_[idx];
    float dv = dvec[ch];

    float sre = 0.f, sim = 0.f;
    const float* up = g_u + ch;
    float* yp = g_y + ch;

    for (int t0 = 0; t0 < L; t0 += 8) {
        float acc[8], uk[8];
#pragma unroll
        for (int k = 0; k < 8; k++) {
            float u = __ldg(up + (t0 + k) * H);
            float t1 = fmaf(bbr, u, fmaf(-aim, sim, are * sre));
            float t2 = fmaf(bbi, u, fmaf(aim, sre, are * sim));
            sre = t1; sim = t2;
            acc[k] = fmaf(-cim, sim, cre * sre);
            uk[k] = u;
        }
        // 8 interleaved butterfly reductions (pipelined SHFL chains)
#pragma unroll
        for (int off = 16; off; off >>= 1) {
#pragma unroll
            for (int k = 0; k < 8; k++)
                acc[k] += __shfl_xor_sync(0xffffffffu, acc[k], off);
        }
#pragma unroll
        for (int k = 0; k < 8; k++) {
            float yv = fmaf(dv, uk[k], 2.f * acc[k]);
            float g = gelu_tanh(yv);
            if (lane == k) yp[(t0 + k) * H] = g;
        }
    }
}

// ---------------------------------------------------------------------------
// Fused dual GEMM + gate + residual:
//   g1 = y @ W1^T + b1 ; g2 = y @ W2^T + b2 ; h += g1 * sigmoid(g2)
// 64x64 tile, BK=32, 256 threads, 4x4 register block per GEMM.
// ---------------------------------------------------------------------------
#define BM 64
#define BN 64
#define BK 32
#define SPAD 68

__global__ __launch_bounds__(256) void gemm_kernel(const float* __restrict__ W1,
                                                   const float* __restrict__ b1,
                                                   const float* __restrict__ W2,
                                                   const float* __restrict__ b2) {
    __shared__ float As[BK][SPAD];
    __shared__ float B1s[BK][SPAD];
    __shared__ float B2s[BK][SPAD];

    int tx = threadIdx.x & 15;
    int ty = threadIdx.x >> 4;
    int n0 = blockIdx.x * BN;
    int m0 = blockIdx.y * BM;

    float acc1[4][4] = {};
    float acc2[4][4] = {};

    for (int k0 = 0; k0 < H; k0 += BK) {
#pragma unroll
        for (int i = 0; i < 8; i++) {
            int id = threadIdx.x + i * 256;
            int r = id >> 5;     // 0..63 (row within tile)
            int k = id & 31;     // 0..31
            As[k][r]  = g_y[(m0 + r) * H + k0 + k];
            B1s[k][r] = W1[(n0 + r) * H + k0 + k];
            B2s[k][r] = W2[(n0 + r) * H + k0 + k];
        }
        __syncthreads();
#pragma unroll
        for (int k = 0; k < BK; k++) {
            float4 a4  = *(const float4*)&As[k][ty * 4];
            float4 c14 = *(const float4*)&B1s[k][tx * 4];
            float4 c24 = *(const float4*)&B2s[k][tx * 4];
            float av[4] = {a4.x, a4.y, a4.z, a4.w};
            float bv1[4] = {c14.x, c14.y, c14.z, c14.w};
            float bv2[4] = {c24.x, c24.y, c24.z, c24.w};
#pragma unroll
            for (int i = 0; i < 4; i++)
#pragma unroll
                for (int j = 0; j < 4; j++) {
                    acc1[i][j] = fmaf(av[i], bv1[j], acc1[i][j]);
                    acc2[i][j] = fmaf(av[i], bv2[j], acc2[i][j]);
                }
        }
        __syncthreads();
    }

#pragma unroll
    for (int i = 0; i < 4; i++) {
        int m = m0 + ty * 4 + i;
#pragma unroll
        for (int j = 0; j < 4; j++) {
            int n = n0 + tx * 4 + j;
            float gg1 = acc1[i][j] + b1[n];
            float gg2 = acc2[i][j] + b2[n];
            float sig = 1.f / (1.f + __expf(-gg2));
            g_h[m * H + n] += gg1 * sig;
        }
    }
}

// ---------------------------------------------------------------------------
// Decoder: out[t][o] = dec_b[o] + sum_j h[t][j] dec_w[o][j]. One warp per row.
// ---------------------------------------------------------------------------
__global__ void dec_kernel(const float* __restrict__ w,
                           const float* __restrict__ b,
                           float* __restrict__ out) {
    int warp = (blockIdx.x * blockDim.x + threadIdx.x) >> 5;
    int lane = threadIdx.x & 31;
    if (warp >= L) return;
    float a0 = 0.f, a1 = 0.f, a2 = 0.f;
#pragma unroll
    for (int j = lane; j < H; j += 32) {
        float hv = g_h[warp * H + j];
        a0 = fmaf(hv, w[j],         a0);
        a1 = fmaf(hv, w[H + j],     a1);
        a2 = fmaf(hv, w[2 * H + j], a2);
    }
#pragma unroll
    for (int off = 16; off; off >>= 1) {
        a0 += __shfl_xor_sync(0xffffffffu, a0, off);
        a1 += __shfl_xor_sync(0xffffffffu, a1, off);
        a2 += __shfl_xor_sync(0xffffffffu, a2, off);
    }
    if (lane == 0) {
        out[warp * 3 + 0] = a0 + b[0];
        out[warp * 3 + 1] = a1 + b[1];
        out[warp * 3 + 2] = a2 + b[2];
    }
}

// ---------------------------------------------------------------------------
extern "C" void kernel_launch(void* const* d_in, const int* in_sizes, int n_in,
                              void* d_out, int out_size) {
    const float* x       = (const float*)d_in[0];
    const float* enc_w   = (const float*)d_in[1];
    const float* enc_b   = (const float*)d_in[2];
    const float* dec_w   = (const float*)d_in[3];
    const float* dec_b   = (const float*)d_in[4];
    const float* norm_w  = (const float*)d_in[5];
    const float* norm_b  = (const float*)d_in[6];
    const float* lam_re  = (const float*)d_in[7];
    const float* lam_im  = (const float*)d_in[8];
    const float* b_re    = (const float*)d_in[9];
    const float* b_im    = (const float*)d_in[10];
    const float* c_re    = (const float*)d_in[11];
    const float* c_im    = (const float*)d_in[12];
    const float* dvec    = (const float*)d_in[13];
    const float* lstep   = (const float*)d_in[14];
    const float* out_w   = (const float*)d_in[15];
    const float* out_b   = (const float*)d_in[16];
    const float* out2_w  = (const float*)d_in[17];
    const float* out2_b  = (const float*)d_in[18];
    float* out = (float*)d_out;

    enc_kernel<<<L, H>>>(x, enc_w, enc_b);

    for (int l = 0; l < NL; l++) {
        ln_kernel<<<L, 256>>>(norm_w + l * H, norm_b + l * H);
        scan_kernel<<<128, 128>>>(lam_re + l * H * NSTATE, lam_im + l * H * NSTATE,
                                  b_re + l * H * NSTATE,  b_im + l * H * NSTATE,
                                  c_re + l * H * NSTATE,  c_im + l * H * NSTATE,
                                  dvec + l * H, lstep + l * H);
        dim3 grid(H / BN, L / BM);
        gemm_kernel<<<grid, 256>>>(out_w + l * H * H, out_b + l * H,
                                   out2_w + l * H * H, out2_b + l * H);
    }

    dec_kernel<<<256, 256>>>(dec_w, dec_b, out);
}

// round 3
// speedup vs baseline: 1.5070x; 1.5070x over previous
#include <cuda_runtime.h>
#include <math.h>

#define L 2048
#define H 512
#define NSTATE 32
#define NL 4
#define INDIM 4
#define OUTDIM 3

#define NCHUNK 16
#define CLEN 128   // L / NCHUNK

// Scratch (allocation-free rule: device globals)
__device__ float g_h[L * H];   // residual stream
__device__ float g_u[L * H];   // layernorm output
__device__ float g_y[L * H];   // scan output (pre-gelu after pass A, post-gelu after pass C)
__device__ float2 g_sfin[H * NCHUNK * NSTATE];   // per-chunk final local state
__device__ float2 g_sinit[H * NCHUNK * NSTATE];  // per-chunk initial (carry-in) state

// ---------------------------------------------------------------------------
// Encoder: h[t][j] = enc_b[j] + sum_k x[t][k] * enc_w[j][k]   (IN = 4)
// ---------------------------------------------------------------------------
__global__ void enc_kernel(const float* __restrict__ x,
                           const float* __restrict__ w,
                           const float* __restrict__ b) {
    int t = blockIdx.x;
    int j = threadIdx.x;
    float4 xr = *(const float4*)(x + t * INDIM);
    float4 wr = *(const float4*)(w + j * INDIM);
    g_h[t * H + j] = b[j] + xr.x * wr.x + xr.y * wr.y + xr.z * wr.z + xr.w * wr.w;
}

// ---------------------------------------------------------------------------
// LayerNorm over H=512 per row. 256 threads, 2 elems each.
// ---------------------------------------------------------------------------
__global__ void ln_kernel(const float* __restrict__ nw,
                          const float* __restrict__ nb) {
    int t = blockIdx.x;
    int tid = threadIdx.x;
    float v0 = g_h[t * H + tid];
    float v1 = g_h[t * H + tid + 256];
    float s = v0 + v1;
    float sq = v0 * v0 + v1 * v1;
#pragma unroll
    for (int off = 16; off; off >>= 1) {
        s  += __shfl_xor_sync(0xffffffffu, s, off);
        sq += __shfl_xor_sync(0xffffffffu, sq, off);
    }
    __shared__ float ss[8], ssq[8];
    int w = tid >> 5;
    if ((tid & 31) == 0) { ss[w] = s; ssq[w] = sq; }
    __syncthreads();
    __shared__ float m_sh, r_sh;
    if (tid == 0) {
        float S = 0.f, Q = 0.f;
#pragma unroll
        for (int i = 0; i < 8; i++) { S += ss[i]; Q += ssq[i]; }
        float m = S * (1.0f / H);
        float var = Q * (1.0f / H) - m * m;
        m_sh = m;
        r_sh = rsqrtf(var + 1e-5f);
    }
    __syncthreads();
    float m = m_sh, r = r_sh;
    g_u[t * H + tid]       = (v0 - m) * r * nw[tid]       + nb[tid];
    g_u[t * H + tid + 256] = (v1 - m) * r * nw[tid + 256] + nb[tid + 256];
}

// ---------------------------------------------------------------------------
// Shared: discretization math per (channel, lane=state)
// ---------------------------------------------------------------------------
struct SSMCoef { float are, aim, bbr, bbi, cre, cim, dv; };

__device__ __forceinline__ SSMCoef load_coef(
    const float* lre_, const float* lim_, const float* bre_, const float* bim_,
    const float* cre_, const float* cim_, const float* dvec, const float* lstep_,
    int ch, int lane)
{
    int idx = ch * NSTATE + lane;
    float lre = lre_[idx], lim = lim_[idx];
    float step = __expf(lstep_[ch]);
    float s2 = 0.5f * step;
    float dr = 1.f - s2 * lre, di = -s2 * lim;
    float inv = 1.f / (dr * dr + di * di);
    float blr = dr * inv, bli = -di * inv;
    float nr = 1.f + s2 * lre, ni = s2 * lim;
    SSMCoef c;
    c.are = blr * nr - bli * ni;
    c.aim = blr * ni + bli * nr;
    float br = bre_[idx], bi = bim_[idx];
    c.bbr = step * (blr * br - bli * bi);
    c.bbi = step * (blr * bi + bli * br);
    c.cre = cre_[idx];
    c.cim = cim_[idx];
    c.dv = dvec[ch];
    return c;
}

__device__ __forceinline__ float gelu_tanh(float yv) {
    float z = 0.7978845608028654f * fmaf(0.044715f * yv, yv * yv, yv);
    z = fminf(fmaxf(z, -15.f), 15.f);
    float e = __expf(2.f * z);
    float th = (e - 1.f) / (e + 1.f);
    return 0.5f * yv * (1.f + th);
}

// ---------------------------------------------------------------------------
// Pass A: local scans. One warp per (channel, chunk). 8192 warps.
// Writes pre-gelu local y to g_y and final local state to g_sfin.
// ---------------------------------------------------------------------------
__global__ void scanA_kernel(const float* __restrict__ lre_, const float* __restrict__ lim_,
                             const float* __restrict__ bre_, const float* __restrict__ bim_,
                             const float* __restrict__ cre_, const float* __restrict__ cim_,
                             const float* __restrict__ dvec, const float* __restrict__ lstep_) {
    int warp = (blockIdx.x * blockDim.x + threadIdx.x) >> 5;
    int lane = threadIdx.x & 31;
    int ch = warp >> 4;          // 0..511
    int chunk = warp & 15;       // 0..15

    SSMCoef cf = load_coef(lre_, lim_, bre_, bim_, cre_, cim_, dvec, lstep_, ch, lane);

    float sre = 0.f, sim = 0.f;
    int tbase = chunk * CLEN;
    const float* up = g_u + ch;
    float* yp = g_y + ch;

    for (int t0 = 0; t0 < CLEN; t0 += 8) {
        float acc[8], uk[8];
#pragma unroll
        for (int k = 0; k < 8; k++) {
            float u = __ldg(up + (tbase + t0 + k) * H);
            float t1 = fmaf(cf.bbr, u, fmaf(-cf.aim, sim, cf.are * sre));
            float t2 = fmaf(cf.bbi, u, fmaf(cf.aim, sre, cf.are * sim));
            sre = t1; sim = t2;
            acc[k] = fmaf(-cf.cim, sim, cf.cre * sre);
            uk[k] = u;
        }
#pragma unroll
        for (int off = 16; off; off >>= 1) {
#pragma unroll
            for (int k = 0; k < 8; k++)
                acc[k] += __shfl_xor_sync(0xffffffffu, acc[k], off);
        }
#pragma unroll
        for (int k = 0; k < 8; k++) {
            if (lane == k) {
                float yv = fmaf(cf.dv, uk[k], 2.f * acc[k]);
                yp[(tbase + t0 + k) * H] = yv;   // pre-gelu
            }
        }
    }
    g_sfin[(ch * NCHUNK + chunk) * NSTATE + lane] = make_float2(sre, sim);
}

// ---------------------------------------------------------------------------
// Pass B: sequential combine across chunks. One warp per channel.
// MUST be launched with 512 warps (H warps).
// ---------------------------------------------------------------------------
__global__ void scanB_kernel(const float* __restrict__ lre_, const float* __restrict__ lim_,
                             const float* __restrict__ bre_, const float* __restrict__ bim_,
                             const float* __restrict__ cre_, const float* __restrict__ cim_,
                             const float* __restrict__ dvec, const float* __restrict__ lstep_) {
    int warp = (blockIdx.x * blockDim.x + threadIdx.x) >> 5;
    int lane = threadIdx.x & 31;
    int ch = warp;
    if (ch >= H) return;

    SSMCoef cf = load_coef(lre_, lim_, bre_, bim_, cre_, cim_, dvec, lstep_, ch, lane);

    // A^CLEN via 7 squarings (CLEN = 128 = 2^7)
    float pr = cf.are, pi = cf.aim;
#pragma unroll
    for (int i = 0; i < 7; i++) {
        float nr = pr * pr - pi * pi;
        float ni = 2.f * pr * pi;
        pr = nr; pi = ni;
    }

    float cr = 0.f, ci = 0.f;  // carry state
#pragma unroll
    for (int c = 0; c < NCHUNK; c++) {
        int idx = (ch * NCHUNK + c) * NSTATE + lane;
        g_sinit[idx] = make_float2(cr, ci);
        float2 f = g_sfin[idx];
        float nr = fmaf(pr, cr, fmaf(-pi, ci, f.x));
        float ni = fmaf(pr, ci, fmaf(pi, cr, f.y));
        cr = nr; ci = ni;
    }
}

// ---------------------------------------------------------------------------
// Pass C: correction + gelu. One warp per (channel, chunk). 8192 warps.
// y_t += 2*Re(sum_n C_n A^(k+1)_n s_init_n), then gelu, written to g_y.
// ---------------------------------------------------------------------------
__global__ void scanC_kernel(const float* __restrict__ lre_, const float* __restrict__ lim_,
                             const float* __restrict__ bre_, const float* __restrict__ bim_,
                             const float* __restrict__ cre_, const float* __restrict__ cim_,
                             const float* __restrict__ dvec, const float* __restrict__ lstep_) {
    int warp = (blockIdx.x * blockDim.x + threadIdx.x) >> 5;
    int lane = threadIdx.x & 31;
    int ch = warp >> 4;
    int chunk = warp & 15;

    SSMCoef cf = load_coef(lre_, lim_, bre_, bim_, cre_, cim_, dvec, lstep_, ch, lane);

    float2 si = g_sinit[(ch * NCHUNK + chunk) * NSTATE + lane];
    // E = C * s_init
    float er = cf.cre * si.x - cf.cim * si.y;
    float ei = cf.cre * si.y + cf.cim * si.x;

    float wr = 1.f, wi = 0.f;   // A^0; multiplied before use -> A^k, k>=1
    int tbase = chunk * CLEN;
    float* yp = g_y + ch;

    for (int t0 = 0; t0 < CLEN; t0 += 8) {
        float acc[8];
#pragma unroll
        for (int k = 0; k < 8; k++) {
            float nr = cf.are * wr - cf.aim * wi;
            float ni = cf.are * wi + cf.aim * wr;
            wr = nr; wi = ni;
            acc[k] = er * wr - ei * wi;
        }
#pragma unroll
        for (int off = 16; off; off >>= 1) {
#pragma unroll
            for (int k = 0; k < 8; k++)
                acc[k] += __shfl_xor_sync(0xffffffffu, acc[k], off);
        }
#pragma unroll
        for (int k = 0; k < 8; k++) {
            if (lane == k) {
                float yv = yp[(tbase + t0 + k) * H] + 2.f * acc[k];
                yp[(tbase + t0 + k) * H] = gelu_tanh(yv);
            }
        }
    }
}

// ---------------------------------------------------------------------------
// Fused dual GEMM + gate + residual. BM=64, BN=64, BK=32, 128 threads.
// Per-thread 8(m) x 4(n), dual accumulators. 1 B of LDS per FMA.
// ---------------------------------------------------------------------------
#define BM 64
#define BN 64
#define BK 32
#define APAD (BM + 4)
#define BPAD (BN + 4)

__global__ __launch_bounds__(128) void gemm_kernel(const float* __restrict__ W1,
                                                   const float* __restrict__ b1,
                                                   const float* __restrict__ W2,
                                                   const float* __restrict__ b2) {
    __shared__ float As[BK][APAD];
    __shared__ float B1s[BK][BPAD];
    __shared__ float B2s[BK][BPAD];

    int tid = threadIdx.x;
    int tx = tid & 15;        // n: 16 * 4 = 64
    int ty = tid >> 4;        // m: 8 * 8 = 64
    int n0 = blockIdx.x * BN;
    int m0 = blockIdx.y * BM;

    float acc1[8][4] = {};
    float acc2[8][4] = {};

    for (int k0 = 0; k0 < H; k0 += BK) {
        // Load tiles: 64x32 floats each = 512 float4 slots, 128 threads x 4
#pragma unroll
        for (int i = 0; i < 4; i++) {
            int slot = tid + i * 128;
            int r = slot >> 3;          // 0..63
            int kk = slot & 7;          // float4 index along k
            float4 av = *(const float4*)&g_y[(m0 + r) * H + k0 + kk * 4];
            float4 b1v = *(const float4*)&W1[(n0 + r) * H + k0 + kk * 4];
            float4 b2v = *(const float4*)&W2[(n0 + r) * H + k0 + kk * 4];
            As[kk * 4 + 0][r] = av.x;  As[kk * 4 + 1][r] = av.y;
            As[kk * 4 + 2][r] = av.z;  As[kk * 4 + 3][r] = av.w;
            B1s[kk * 4 + 0][r] = b1v.x; B1s[kk * 4 + 1][r] = b1v.y;
            B1s[kk * 4 + 2][r] = b1v.z; B1s[kk * 4 + 3][r] = b1v.w;
            B2s[kk * 4 + 0][r] = b2v.x; B2s[kk * 4 + 1][r] = b2v.y;
            B2s[kk * 4 + 2][r] = b2v.z; B2s[kk * 4 + 3][r] = b2v.w;
        }
        __syncthreads();
#pragma unroll
        for (int k = 0; k < BK; k++) {
            float4 a0 = *(const float4*)&As[k][ty * 8];
            float4 a1 = *(const float4*)&As[k][ty * 8 + 4];
            float4 c1 = *(const float4*)&B1s[k][tx * 4];
            float4 c2 = *(const float4*)&B2s[k][tx * 4];
            float av[8] = {a0.x, a0.y, a0.z, a0.w, a1.x, a1.y, a1.z, a1.w};
            float bv1[4] = {c1.x, c1.y, c1.z, c1.w};
            float bv2[4] = {c2.x, c2.y, c2.z, c2.w};
#pragma unroll
            for (int i = 0; i < 8; i++)
#pragma unroll
                for (int j = 0; j < 4; j++) {
                    acc1[i][j] = fmaf(av[i], bv1[j], acc1[i][j]);
                    acc2[i][j] = fmaf(av[i], bv2[j], acc2[i][j]);
                }
        }
        __syncthreads();
    }

#pragma unroll
    for (int i = 0; i < 8; i++) {
        int m = m0 + ty * 8 + i;
#pragma unroll
        for (int j = 0; j < 4; j++) {
            int n = n0 + tx * 4 + j;
            float gg1 = acc1[i][j] + b1[n];
            float gg2 = acc2[i][j] + b2[n];
            float sig = 1.f / (1.f + __expf(-gg2));
            g_h[m * H + n] += gg1 * sig;
        }
    }
}

// ---------------------------------------------------------------------------
// Decoder: out[t][o] = dec_b[o] + sum_j h[t][j] dec_w[o][j]. One warp per row.
// ---------------------------------------------------------------------------
__global__ void dec_kernel(const float* __restrict__ w,
                           const float* __restrict__ b,
                           float* __restrict__ out) {
    int warp = (blockIdx.x * blockDim.x + threadIdx.x) >> 5;
    int lane = threadIdx.x & 31;
    if (warp >= L) return;
    float a0 = 0.f, a1 = 0.f, a2 = 0.f;
#pragma unroll
    for (int j = lane; j < H; j += 32) {
        float hv = g_h[warp * H + j];
        a0 = fmaf(hv, w[j],         a0);
        a1 = fmaf(hv, w[H + j],     a1);
        a2 = fmaf(hv, w[2 * H + j], a2);
    }
#pragma unroll
    for (int off = 16; off; off >>= 1) {
        a0 += __shfl_xor_sync(0xffffffffu, a0, off);
        a1 += __shfl_xor_sync(0xffffffffu, a1, off);
        a2 += __shfl_xor_sync(0xffffffffu, a2, off);
    }
    if (lane == 0) {
        out[warp * 3 + 0] = a0 + b[0];
        out[warp * 3 + 1] = a1 + b[1];
        out[warp * 3 + 2] = a2 + b[2];
    }
}

// ---------------------------------------------------------------------------
extern "C" void kernel_launch(void* const* d_in, const int* in_sizes, int n_in,
                              void* d_out, int out_size) {
    const float* x       = (const float*)d_in[0];
    const float* enc_w   = (const float*)d_in[1];
    const float* enc_b   = (const float*)d_in[2];
    const float* dec_w   = (const float*)d_in[3];
    const float* dec_b   = (const float*)d_in[4];
    const float* norm_w  = (const float*)d_in[5];
    const float* norm_b  = (const float*)d_in[6];
    const float* lam_re  = (const float*)d_in[7];
    const float* lam_im  = (const float*)d_in[8];
    const float* b_re    = (const float*)d_in[9];
    const float* b_im    = (const float*)d_in[10];
    const float* c_re    = (const float*)d_in[11];
    const float* c_im    = (const float*)d_in[12];
    const float* dvec    = (const float*)d_in[13];
    const float* lstep   = (const float*)d_in[14];
    const float* out_w   = (const float*)d_in[15];
    const float* out_b   = (const float*)d_in[16];
    const float* out2_w  = (const float*)d_in[17];
    const float* out2_b  = (const float*)d_in[18];
    float* out = (float*)d_out;

    enc_kernel<<<L, H>>>(x, enc_w, enc_b);

    for (int l = 0; l < NL; l++) {
        const float* lre = lam_re + l * H * NSTATE;
        const float* lim = lam_im + l * H * NSTATE;
        const float* bre = b_re + l * H * NSTATE;
        const float* bim = b_im + l * H * NSTATE;
        const float* cre = c_re + l * H * NSTATE;
        const float* cim = c_im + l * H * NSTATE;
        const float* dv  = dvec + l * H;
        const float* ls  = lstep + l * H;

        ln_kernel<<<L, 256>>>(norm_w + l * H, norm_b + l * H);
        scanA_kernel<<<1024, 256>>>(lre, lim, bre, bim, cre, cim, dv, ls);
        scanB_kernel<<<128, 128>>>(lre, lim, bre, bim, cre, cim, dv, ls);  // 512 warps
        scanC_kernel<<<1024, 256>>>(lre, lim, bre, bim, cre, cim, dv, ls);
        dim3 grid(H / BN, L / BM);
        gemm_kernel<<<grid, 128>>>(out_w + l * H * H, out_b + l * H,
                                   out2_w + l * H * H, out2_b + l * H);
    }

    dec_kernel<<<256, 256>>>(dec_w, dec_b, out);
}

// round 4
// speedup vs baseline: 3.4027x; 2.2579x over previous
#include <cuda_runtime.h>
#include <math.h>

#define L 2048
#define H 512
#define NSTATE 32
#define NL 4
#define INDIM 4
#define OUTDIM 3

#define NCHUNK 16
#define CLEN 128   // L / NCHUNK

// Scratch (allocation-free rule: device globals)
__device__ float g_h[L * H];   // residual stream
__device__ float g_u[L * H];   // layernorm output
__device__ float g_y[L * H];   // gelu(scan output)

// ---------------------------------------------------------------------------
// Encoder
// ---------------------------------------------------------------------------
__global__ void enc_kernel(const float* __restrict__ x,
                           const float* __restrict__ w,
                           const float* __restrict__ b) {
    int t = blockIdx.x;
    int j = threadIdx.x;
    float4 xr = *(const float4*)(x + t * INDIM);
    float4 wr = *(const float4*)(w + j * INDIM);
    g_h[t * H + j] = b[j] + xr.x * wr.x + xr.y * wr.y + xr.z * wr.z + xr.w * wr.w;
}

// ---------------------------------------------------------------------------
// LayerNorm over H=512 per row
// ---------------------------------------------------------------------------
__global__ void ln_kernel(const float* __restrict__ nw,
                          const float* __restrict__ nb) {
    int t = blockIdx.x;
    int tid = threadIdx.x;
    float v0 = g_h[t * H + tid];
    float v1 = g_h[t * H + tid + 256];
    float s = v0 + v1;
    float sq = v0 * v0 + v1 * v1;
#pragma unroll
    for (int off = 16; off; off >>= 1) {
        s  += __shfl_xor_sync(0xffffffffu, s, off);
        sq += __shfl_xor_sync(0xffffffffu, sq, off);
    }
    __shared__ float ss[8], ssq[8];
    int w = tid >> 5;
    if ((tid & 31) == 0) { ss[w] = s; ssq[w] = sq; }
    __syncthreads();
    __shared__ float m_sh, r_sh;
    if (tid == 0) {
        float S = 0.f, Q = 0.f;
#pragma unroll
        for (int i = 0; i < 8; i++) { S += ss[i]; Q += ssq[i]; }
        float m = S * (1.0f / H);
        float var = Q * (1.0f / H) - m * m;
        m_sh = m;
        r_sh = rsqrtf(var + 1e-5f);
    }
    __syncthreads();
    float m = m_sh, r = r_sh;
    g_u[t * H + tid]       = (v0 - m) * r * nw[tid]       + nb[tid];
    g_u[t * H + tid + 256] = (v1 - m) * r * nw[tid + 256] + nb[tid + 256];
}

// ---------------------------------------------------------------------------
// Discretization coefficients per (channel, lane=state)
// ---------------------------------------------------------------------------
struct SSMCoef { float are, aim, bbr, bbi, cre, cim, dv; };

__device__ __forceinline__ SSMCoef load_coef(
    const float* lre_, const float* lim_, const float* bre_, const float* bim_,
    const float* cre_, const float* cim_, const float* dvec, const float* lstep_,
    int ch, int lane)
{
    int idx = ch * NSTATE + lane;
    float lre = lre_[idx], lim = lim_[idx];
    float step = __expf(lstep_[ch]);
    float s2 = 0.5f * step;
    float dr = 1.f - s2 * lre, di = -s2 * lim;
    float inv = 1.f / (dr * dr + di * di);
    float blr = dr * inv, bli = -di * inv;
    float nr = 1.f + s2 * lre, ni = s2 * lim;
    SSMCoef c;
    c.are = blr * nr - bli * ni;
    c.aim = blr * ni + bli * nr;
    float br = bre_[idx], bi = bim_[idx];
    c.bbr = step * (blr * br - bli * bi);
    c.bbi = step * (blr * bi + bli * br);
    c.cre = cre_[idx];
    c.cim = cim_[idx];
    c.dv = dvec[ch];
    return c;
}

__device__ __forceinline__ float gelu_tanh(float yv) {
    float z = 0.7978845608028654f * fmaf(0.044715f * yv, yv * yv, yv);
    z = fminf(fmaxf(z, -15.f), 15.f);
    float e = __expf(2.f * z);
    float th = (e - 1.f) / (e + 1.f);
    return 0.5f * yv * (1.f + th);
}

// Merge-reduce: combine a (kept on lanes with bit 'off' clear) and b (bit set),
// each summed over the off-partner pair.
__device__ __forceinline__ float merge2(float a, float b, int off, int lane) {
    float t = (lane & off) ? a : b;
    t = __shfl_xor_sync(0xffffffffu, t, off);
    return ((lane & off) ? b : a) + t;
}

// Reduce 8 accumulators across the warp with 9 shuffles. Result: each lane
// holds the full 32-lane sum of acc[myk], myk = bit16 + 2*bit8 + 4*bit4.
__device__ __forceinline__ float reduce8(const float* acc, int lane) {
    float m01 = merge2(acc[0], acc[1], 16, lane);
    float m23 = merge2(acc[2], acc[3], 16, lane);
    float m45 = merge2(acc[4], acc[5], 16, lane);
    float m67 = merge2(acc[6], acc[7], 16, lane);
    float n0  = merge2(m01, m23, 8, lane);
    float n1  = merge2(m45, m67, 8, lane);
    float p   = merge2(n0, n1, 4, lane);
    p += __shfl_xor_sync(0xffffffffu, p, 2);
    p += __shfl_xor_sync(0xffffffffu, p, 1);
    return p;
}

// ---------------------------------------------------------------------------
// Fused scan: one block per channel (512 threads = 16 warps, warp = chunk).
// Phase A: local scans, y kept in registers. Phase B: smem chunk combine
// (warp 0). Phase C: correction + gelu + single write to g_y.
// ---------------------------------------------------------------------------
__global__ __launch_bounds__(512) void scan_fused_kernel(
        const float* __restrict__ lre_, const float* __restrict__ lim_,
        const float* __restrict__ bre_, const float* __restrict__ bim_,
        const float* __restrict__ cre_, const float* __restrict__ cim_,
        const float* __restrict__ dvec, const float* __restrict__ lstep_) {
    __shared__ float2 st[NCHUNK][NSTATE];

    int ch = blockIdx.x;
    int wid = threadIdx.x >> 5;      // chunk
    int lane = threadIdx.x & 31;     // state

    SSMCoef cf = load_coef(lre_, lim_, bre_, bim_, cre_, cim_, dvec, lstep_, ch, lane);
    int myk = ((lane >> 4) & 1) | (((lane >> 3) & 1) << 1) | (((lane >> 2) & 1) << 2);

    int tbase = wid * CLEN;
    const float* up = g_u + ch;
    float* yp = g_y + ch;

    float yreg[16];
    float sre = 0.f, sim = 0.f;

    // ---- Phase A: local scan ----
#pragma unroll
    for (int b = 0; b < 16; b++) {
        int t0 = tbase + b * 8;
        float acc[8], uk[8];
#pragma unroll
        for (int k = 0; k < 8; k++) {
            float u = __ldg(up + (t0 + k) * H);
            float t1 = fmaf(cf.bbr, u, fmaf(-cf.aim, sim, cf.are * sre));
            float t2 = fmaf(cf.bbi, u, fmaf(cf.aim, sre, cf.are * sim));
            sre = t1; sim = t2;
            acc[k] = fmaf(-cf.cim, sim, cf.cre * sre);
            uk[k] = u;
        }
        float red = reduce8(acc, lane);
        // select u for this lane's myk (mirrors the merge network)
        float s01 = (lane & 16) ? uk[1] : uk[0];
        float s23 = (lane & 16) ? uk[3] : uk[2];
        float s45 = (lane & 16) ? uk[5] : uk[4];
        float s67 = (lane & 16) ? uk[7] : uk[6];
        float t0s = (lane & 8) ? s23 : s01;
        float t1s = (lane & 8) ? s67 : s45;
        float usel = (lane & 4) ? t1s : t0s;
        yreg[b] = fmaf(cf.dv, usel, 2.f * red);
    }
    st[wid][lane] = make_float2(sre, sim);
    __syncthreads();

    // ---- Phase B: sequential chunk combine (warp 0), in-place in smem ----
    if (wid == 0) {
        float pr = cf.are, pi = cf.aim;
#pragma unroll
        for (int i = 0; i < 7; i++) {   // A^128
            float nr = pr * pr - pi * pi;
            float ni = 2.f * pr * pi;
            pr = nr; pi = ni;
        }
        float cr = 0.f, ci = 0.f;
#pragma unroll
        for (int c = 0; c < NCHUNK; c++) {
            float2 f = st[c][lane];
            st[c][lane] = make_float2(cr, ci);   // carry-in for chunk c
            float nr = fmaf(pr, cr, fmaf(-pi, ci, f.x));
            float ni = fmaf(pr, ci, fmaf(pi, cr, f.y));
            cr = nr; ci = ni;
        }
    }
    __syncthreads();

    // ---- Phase C: correction + gelu + store ----
    float2 si = st[wid][lane];
    float er = cf.cre * si.x - cf.cim * si.y;
    float ei = cf.cre * si.y + cf.cim * si.x;
    float wr = 1.f, wi = 0.f;

#pragma unroll
    for (int b = 0; b < 16; b++) {
        float acc[8];
#pragma unroll
        for (int k = 0; k < 8; k++) {
            float nr = cf.are * wr - cf.aim * wi;
            float ni = cf.are * wi + cf.aim * wr;
            wr = nr; wi = ni;
            acc[k] = er * wr - ei * wi;
        }
        float corr = reduce8(acc, lane);
        float yv = yreg[b] + 2.f * corr;
        if ((lane & 3) == 0)
            yp[(tbase + b * 8 + myk) * H] = gelu_tanh(yv);
    }
}

// ---------------------------------------------------------------------------
// Fused dual GEMM + gate + residual. BM=64, BN=32, BK=32, 128 threads,
// 512 blocks, double-buffered smem with register prefetch.
// ---------------------------------------------------------------------------
#define BM 64
#define BN 32
#define BK 32
#define APAD (BM + 4)
#define BPAD (BN + 4)
#define NKIT (H / BK)

__global__ __launch_bounds__(128) void gemm_kernel(const float* __restrict__ W1,
                                                   const float* __restrict__ b1,
                                                   const float* __restrict__ W2,
                                                   const float* __restrict__ b2) {
    __shared__ float As[2][BK][APAD];
    __shared__ float B1s[2][BK][BPAD];
    __shared__ float B2s[2][BK][BPAD];

    int tid = threadIdx.x;
    int tx = tid & 15;        // n: 16 * 2 = 32
    int ty = tid >> 4;        // m: 8 * 8 = 64
    int n0 = blockIdx.x * BN;
    int m0 = blockIdx.y * BM;

    float acc1[8][2] = {};
    float acc2[8][2] = {};

    // load-slot mapping
    int ra = tid >> 3;              // base row for A slots (0..15, +16 per i)
    int kk = tid & 7;               // float4 index along k

    // prologue: stage 0
#pragma unroll
    for (int i = 0; i < 4; i++) {
        int r = ra + i * 16;
        float4 v = *(const float4*)&g_y[(m0 + r) * H + kk * 4];
        As[0][kk * 4 + 0][r] = v.x; As[0][kk * 4 + 1][r] = v.y;
        As[0][kk * 4 + 2][r] = v.z; As[0][kk * 4 + 3][r] = v.w;
    }
#pragma unroll
    for (int i = 0; i < 2; i++) {
        int r = ra + i * 16;
        float4 v1 = *(const float4*)&W1[(n0 + r) * H + kk * 4];
        float4 v2 = *(const float4*)&W2[(n0 + r) * H + kk * 4];
        B1s[0][kk * 4 + 0][r] = v1.x; B1s[0][kk * 4 + 1][r] = v1.y;
        B1s[0][kk * 4 + 2][r] = v1.z; B1s[0][kk * 4 + 3][r] = v1.w;
        B2s[0][kk * 4 + 0][r] = v2.x; B2s[0][kk * 4 + 1][r] = v2.y;
        B2s[0][kk * 4 + 2][r] = v2.z; B2s[0][kk * 4 + 3][r] = v2.w;
    }
    __syncthreads();

    for (int it = 0; it < NKIT; it++) {
        int cur = it & 1;
        int nxt = cur ^ 1;

        float4 pa[4], pb1[2], pb2[2];
        if (it + 1 < NKIT) {
            int k0n = (it + 1) * BK;
#pragma unroll
            for (int i = 0; i < 4; i++)
                pa[i] = *(const float4*)&g_y[(m0 + ra + i * 16) * H + k0n + kk * 4];
#pragma unroll
            for (int i = 0; i < 2; i++) {
                pb1[i] = *(const float4*)&W1[(n0 + ra + i * 16) * H + k0n + kk * 4];
                pb2[i] = *(const float4*)&W2[(n0 + ra + i * 16) * H + k0n + kk * 4];
            }
        }

#pragma unroll
        for (int k = 0; k < BK; k++) {
            float4 a0 = *(const float4*)&As[cur][k][ty * 8];
            float4 a1 = *(const float4*)&As[cur][k][ty * 8 + 4];
            float2 c1 = *(const float2*)&B1s[cur][k][tx * 2];
            float2 c2 = *(const float2*)&B2s[cur][k][tx * 2];
            float av[8] = {a0.x, a0.y, a0.z, a0.w, a1.x, a1.y, a1.z, a1.w};
#pragma unroll
            for (int i = 0; i < 8; i++) {
                acc1[i][0] = fmaf(av[i], c1.x, acc1[i][0]);
                acc1[i][1] = fmaf(av[i], c1.y, acc1[i][1]);
                acc2[i][0] = fmaf(av[i], c2.x, acc2[i][0]);
                acc2[i][1] = fmaf(av[i], c2.y, acc2[i][1]);
            }
        }

        if (it + 1 < NKIT) {
#pragma unroll
            for (int i = 0; i < 4; i++) {
                int r = ra + i * 16;
                As[nxt][kk * 4 + 0][r] = pa[i].x; As[nxt][kk * 4 + 1][r] = pa[i].y;
                As[nxt][kk * 4 + 2][r] = pa[i].z; As[nxt][kk * 4 + 3][r] = pa[i].w;
            }
#pragma unroll
            for (int i = 0; i < 2; i++) {
                int r = ra + i * 16;
                B1s[nxt][kk * 4 + 0][r] = pb1[i].x; B1s[nxt][kk * 4 + 1][r] = pb1[i].y;
                B1s[nxt][kk * 4 + 2][r] = pb1[i].z; B1s[nxt][kk * 4 + 3][r] = pb1[i].w;
                B2s[nxt][kk * 4 + 0][r] = pb2[i].x; B2s[nxt][kk * 4 + 1][r] = pb2[i].y;
                B2s[nxt][kk * 4 + 2][r] = pb2[i].z; B2s[nxt][kk * 4 + 3][r] = pb2[i].w;
            }
            __syncthreads();
        }
    }

#pragma unroll
    for (int i = 0; i < 8; i++) {
        int m = m0 + ty * 8 + i;
#pragma unroll
        for (int j = 0; j < 2; j++) {
            int n = n0 + tx * 2 + j;
            float gg1 = acc1[i][j] + b1[n];
            float gg2 = acc2[i][j] + b2[n];
            float sig = 1.f / (1.f + __expf(-gg2));
            g_h[m * H + n] += gg1 * sig;
        }
    }
}

// ---------------------------------------------------------------------------
// Decoder
// ---------------------------------------------------------------------------
__global__ void dec_kernel(const float* __restrict__ w,
                           const float* __restrict__ b,
                           float* __restrict__ out) {
    int warp = (blockIdx.x * blockDim.x + threadIdx.x) >> 5;
    int lane = threadIdx.x & 31;
    if (warp >= L) return;
    float a0 = 0.f, a1 = 0.f, a2 = 0.f;
#pragma unroll
    for (int j = lane; j < H; j += 32) {
        float hv = g_h[warp * H + j];
        a0 = fmaf(hv, w[j],         a0);
        a1 = fmaf(hv, w[H + j],     a1);
        a2 = fmaf(hv, w[2 * H + j], a2);
    }
#pragma unroll
    for (int off = 16; off; off >>= 1) {
        a0 += __shfl_xor_sync(0xffffffffu, a0, off);
        a1 += __shfl_xor_sync(0xffffffffu, a1, off);
        a2 += __shfl_xor_sync(0xffffffffu, a2, off);
    }
    if (lane == 0) {
        out[warp * 3 + 0] = a0 + b[0];
        out[warp * 3 + 1] = a1 + b[1];
        out[warp * 3 + 2] = a2 + b[2];
    }
}

// ---------------------------------------------------------------------------
extern "C" void kernel_launch(void* const* d_in, const int* in_sizes, int n_in,
                              void* d_out, int out_size) {
    const float* x       = (const float*)d_in[0];
    const float* enc_w   = (const float*)d_in[1];
    const float* enc_b   = (const float*)d_in[2];
    const float* dec_w   = (const float*)d_in[3];
    const float* dec_b   = (const float*)d_in[4];
    const float* norm_w  = (const float*)d_in[5];
    const float* norm_b  = (const float*)d_in[6];
    const float* lam_re  = (const float*)d_in[7];
    const float* lam_im  = (const float*)d_in[8];
    const float* b_re    = (const float*)d_in[9];
    const float* b_im    = (const float*)d_in[10];
    const float* c_re    = (const float*)d_in[11];
    const float* c_im    = (const float*)d_in[12];
    const float* dvec    = (const float*)d_in[13];
    const float* lstep   = (const float*)d_in[14];
    const float* out_w   = (const float*)d_in[15];
    const float* out_b   = (const float*)d_in[16];
    const float* out2_w  = (const float*)d_in[17];
    const float* out2_b  = (const float*)d_in[18];
    float* out = (float*)d_out;

    enc_kernel<<<L, H>>>(x, enc_w, enc_b);

    for (int l = 0; l < NL; l++) {
        ln_kernel<<<L, 256>>>(norm_w + l * H, norm_b + l * H);
        scan_fused_kernel<<<H, 512>>>(lam_re + l * H * NSTATE, lam_im + l * H * NSTATE,
                                      b_re + l * H * NSTATE,  b_im + l * H * NSTATE,
                                      c_re + l * H * NSTATE,  c_im + l * H * NSTATE,
                                      dvec + l * H, lstep + l * H);
        dim3 grid(H / BN, L / BM);
        gemm_kernel<<<grid, 128>>>(out_w + l * H * H, out_b + l * H,
                                   out2_w + l * H * H, out2_b + l * H);
    }

    dec_kernel<<<256, 256>>>(dec_w, dec_b, out);
}